// round 6
// baseline (speedup 1.0000x reference)
#include <cuda_runtime.h>
#include <cuda_bf16.h>

// ChaosClock analytic collapse (validated, rel_err ~2e-7):
//   logits = GRU(x[:,0,:]@Wp.T+bp, h=0) @ Wh[:, :8].T + bh
// R6: barrier-free warp-autonomous design. Each warp redundantly computes u
// for its batch (4 warps/batch, x row dedups in cache) and owns a 250-class
// quarter of the epilogue. No shared memory, no __syncthreads: per-warp
// critical path = own x load -> ~60cy math -> FMAs on prefetched Wh regs.

#define BPC  2           // batches per CTA (2 batches x 4 quarters = 8 warps)
#define CPT  8           // c-values per lane (8*32 = 256 >= 250 quarter size)
#define QSZ  250         // classes per quarter (C = 1000)

__global__ void __launch_bounds__(256) chaos_clock_kernel(
    const float* __restrict__ x,      // (B,T,D)
    const float* __restrict__ Wp,     // (8,D)
    const float* __restrict__ bp,     // (8)
    const float* __restrict__ W_ih,   // (24,8)
    const float* __restrict__ b_ih,   // (24)
    const float* __restrict__ b_hh,   // (24)
    const float* __restrict__ Wh,     // (C,32)
    const float* __restrict__ bh,     // (C)
    float* __restrict__ out,          // (B,C)
    int T, int D, int C)
{
    const int tid  = threadIdx.x;
    const int warp = tid >> 5;
    const int lane = tid & 31;
    const int b0   = blockIdx.x * BPC;

    const int bw   = warp & (BPC - 1);   // batch within CTA
    const int qtr  = warp >> 1;          // class quarter 0..3
    const int b    = b0 + bw;

    // ---- Issue x row loads first (DRAM, longest chain edge).
    // lane = s*4 + q: partial dot for output s over elems [q*16, q*16+16).
    const int s = lane >> 2;
    const int q = lane & 3;
    const float4* xp4 = reinterpret_cast<const float4*>(x + (size_t)b * T * D + q * 16);
    float4 xq[4];
    #pragma unroll
    for (int i = 0; i < 4; ++i) xq[i] = xp4[i];

    // ---- Prefetch this warp's Wh quarter into registers (independent of u).
    const int c0 = qtr * QSZ;
    float4 w0[CPT], w1[CPT];
    float  bb[CPT];
    #pragma unroll
    for (int k = 0; k < CPT; ++k) {
        int cc = lane + k * 32;
        cc = (cc < QSZ) ? cc : (QSZ - 1);       // clamp (duplicate load)
        const int c = c0 + cc;
        const float4* w = reinterpret_cast<const float4*>(Wh + (size_t)c * 32);
        w0[k] = w[0];
        w1[k] = w[1];
        bb[k] = bh[c];
    }

    // ---- Phase 1 (per-warp, redundant across quarters): u for batch b.
    const float4* wp4 = reinterpret_cast<const float4*>(Wp + s * D + q * 16);
    float acc = 0.f;
    #pragma unroll
    for (int i = 0; i < 4; ++i) {
        float4 wv = wp4[i];
        acc += xq[i].x * wv.x + xq[i].y * wv.y + xq[i].z * wv.z + xq[i].w * wv.w;
    }
    acc += __shfl_xor_sync(0xffffffffu, acc, 1);
    acc += __shfl_xor_sync(0xffffffffu, acc, 2);

    float inp[8];
    #pragma unroll
    for (int ss = 0; ss < 8; ++ss)
        inp[ss] = __shfl_sync(0xffffffffu, acc, ss * 4) + bp[ss];

    float gi = 0.0f;
    if (lane < 24) {
        gi = b_ih[lane];
        const float* wrow = W_ih + lane * 8;
        #pragma unroll
        for (int ss = 0; ss < 8; ++ss) gi += inp[ss] * wrow[ss];
    }
    float gz = __shfl_sync(0xffffffffu, gi, lane + 8);   // gi[8..15] -> lanes 0..7
    float gn = __shfl_sync(0xffffffffu, gi, lane + 16);  // gi[16..23] -> lanes 0..7

    float uval = 0.0f;
    if (lane < 8) {
        float r  = __fdividef(1.0f, 1.0f + __expf(-(gi + b_hh[lane])));
        float z  = __fdividef(1.0f, 1.0f + __expf(-(gz + b_hh[lane + 8])));
        float na = gn + r * b_hh[lane + 16];
        float n  = __fdividef(2.0f, 1.0f + __expf(-2.0f * na)) - 1.0f;
        uval = (1.0f - z) * n;   // + z*h with h = 0
    }
    // broadcast u[0..7] from lanes 0..7 to all lanes
    float u[8];
    #pragma unroll
    for (int ss = 0; ss < 8; ++ss)
        u[ss] = __shfl_sync(0xffffffffu, uval, ss);

    // ---- Phase 2: epilogue for this warp's (batch, quarter) tile.
    float* orow = out + (size_t)b * C + c0;
    #pragma unroll
    for (int k = 0; k < CPT; ++k) {
        const int cc = lane + k * 32;
        float r = bb[k];
        r += u[0] * w0[k].x + u[1] * w0[k].y + u[2] * w0[k].z + u[3] * w0[k].w;
        r += u[4] * w1[k].x + u[5] * w1[k].y + u[6] * w1[k].z + u[7] * w1[k].w;
        if (cc < QSZ) orow[cc] = r;
    }
}

extern "C" void kernel_launch(void* const* d_in, const int* in_sizes, int n_in,
                              void* d_out, int out_size) {
    const float* x    = (const float*)d_in[0];
    // d_in[1] jump_rand, d_in[5] W_hh, d_in[8] Wj, d_in[9] bj: provably dead
    const float* Wp   = (const float*)d_in[2];
    const float* bp   = (const float*)d_in[3];
    const float* W_ih = (const float*)d_in[4];
    const float* b_ih = (const float*)d_in[6];
    const float* b_hh = (const float*)d_in[7];
    const float* Wh   = (const float*)d_in[10];
    const float* bh   = (const float*)d_in[11];
    float* out = (float*)d_out;

    const int C = in_sizes[11];                 // 1000
    const int B = out_size / C;                 // 512
    const int D = in_sizes[2] / 8;              // 64
    const int T = in_sizes[0] / (B * D);        // 512

    chaos_clock_kernel<<<B / BPC, 256>>>(x, Wp, bp, W_ih, b_ih, b_hh, Wh, bh, out, T, D, C);
}

// round 8
// speedup vs baseline: 1.2610x; 1.2610x over previous
#include <cuda_runtime.h>
#include <cuda_bf16.h>

// ChaosClock analytic collapse (validated, rel_err ~2e-7):
//   logits = GRU(x[:,0,:]@Wp.T+bp, h=0) @ Wh[:, :8].T + bh
// R7: two-kernel split (decisive experiment vs. fixed-overhead floor).
//   A: warp-per-batch computes u -> __device__ scratch (16 KB).
//   B: proven R4/R5 epilogue; reads u from L2-hot scratch, no in-kernel
//      dependency between x-load chain and Wh-load chain at all.

#define BPC  4           // batches per CTA in kernel B
#define CPT  4           // c-values per thread in kernel B (4*256 >= 1000)

__device__ float g_u[512 * 8];   // u[b][s] scratch

// ---------- Kernel A: u = GRU(x@Wp.T+bp, h=0), one warp per batch ----------
__global__ void __launch_bounds__(256) ua_kernel(
    const float* __restrict__ x,      // (B,T,D)
    const float* __restrict__ Wp,     // (8,D)
    const float* __restrict__ bp,     // (8)
    const float* __restrict__ W_ih,   // (24,8)
    const float* __restrict__ b_ih,   // (24)
    const float* __restrict__ b_hh,   // (24)
    int T, int D)
{
    const int warp = threadIdx.x >> 5;
    const int lane = threadIdx.x & 31;
    const int b    = blockIdx.x * 8 + warp;

    // lane = s*4 + q : partial dot for output s over elems [q*16, q*16+16)
    const int s = lane >> 2;
    const int q = lane & 3;
    const float4* xp4 = reinterpret_cast<const float4*>(x + (size_t)b * T * D + q * 16);
    float4 xq[4];
    #pragma unroll
    for (int i = 0; i < 4; ++i) xq[i] = xp4[i];

    const float4* wp4 = reinterpret_cast<const float4*>(Wp + s * D + q * 16);
    float acc = 0.f;
    #pragma unroll
    for (int i = 0; i < 4; ++i) {
        float4 wv = wp4[i];
        acc += xq[i].x * wv.x + xq[i].y * wv.y + xq[i].z * wv.z + xq[i].w * wv.w;
    }
    acc += __shfl_xor_sync(0xffffffffu, acc, 1);
    acc += __shfl_xor_sync(0xffffffffu, acc, 2);

    float inp[8];
    #pragma unroll
    for (int ss = 0; ss < 8; ++ss)
        inp[ss] = __shfl_sync(0xffffffffu, acc, ss * 4) + bp[ss];

    float gi = 0.0f;
    if (lane < 24) {
        gi = b_ih[lane];
        const float* wrow = W_ih + lane * 8;
        #pragma unroll
        for (int ss = 0; ss < 8; ++ss) gi += inp[ss] * wrow[ss];
    }
    float gz = __shfl_sync(0xffffffffu, gi, lane + 8);   // gi[8..15] -> lanes 0..7
    float gn = __shfl_sync(0xffffffffu, gi, lane + 16);  // gi[16..23] -> lanes 0..7

    if (lane < 8) {
        float r  = __fdividef(1.0f, 1.0f + __expf(-(gi + b_hh[lane])));
        float z  = __fdividef(1.0f, 1.0f + __expf(-(gz + b_hh[lane + 8])));
        float na = gn + r * b_hh[lane + 16];
        float n  = __fdividef(2.0f, 1.0f + __expf(-2.0f * na)) - 1.0f;
        g_u[b * 8 + lane] = (1.0f - z) * n;   // + z*h with h = 0
    }
}

// ---------- Kernel B: out[b,c] = u[b] . Wh[c,0:8] + bh[c] ----------
__global__ void __launch_bounds__(256) ep_kernel(
    const float* __restrict__ Wh,     // (C,32)
    const float* __restrict__ bh,     // (C)
    float* __restrict__ out,          // (B,C)
    int C)
{
    const int tid = threadIdx.x;
    const int b0  = blockIdx.x * BPC;

    // Prefetch Wh tile (DRAM/L2, longest edge) — issue first.
    float4 w0[CPT], w1[CPT];
    float  bb[CPT];
    #pragma unroll
    for (int k = 0; k < CPT; ++k) {
        int c = tid + k * 256;
        c = (c < C) ? c : (C - 1);            // clamp; store predicated later
        const float4* w = reinterpret_cast<const float4*>(Wh + (size_t)c * 32);
        w0[k] = w[0];
        w1[k] = w[1];
        bb[k] = bh[c];
    }

    // u for the CTA's 4 batches: 8 float4 uniform loads (L2-hot, broadcast).
    float4 uv[BPC][2];
    const float4* up = reinterpret_cast<const float4*>(g_u + b0 * 8);
    #pragma unroll
    for (int nb = 0; nb < BPC; ++nb) {
        uv[nb][0] = up[nb * 2 + 0];
        uv[nb][1] = up[nb * 2 + 1];
    }

    #pragma unroll
    for (int k = 0; k < CPT; ++k) {
        const int c = tid + k * 256;
        if (c >= C) break;
        #pragma unroll
        for (int nb = 0; nb < BPC; ++nb) {
            float acc = bb[k];
            acc += uv[nb][0].x * w0[k].x + uv[nb][0].y * w0[k].y
                 + uv[nb][0].z * w0[k].z + uv[nb][0].w * w0[k].w;
            acc += uv[nb][1].x * w1[k].x + uv[nb][1].y * w1[k].y
                 + uv[nb][1].z * w1[k].z + uv[nb][1].w * w1[k].w;
            out[(size_t)(b0 + nb) * C + c] = acc;
        }
    }
}

extern "C" void kernel_launch(void* const* d_in, const int* in_sizes, int n_in,
                              void* d_out, int out_size) {
    const float* x    = (const float*)d_in[0];
    // d_in[1] jump_rand, d_in[5] W_hh, d_in[8] Wj, d_in[9] bj: provably dead
    const float* Wp   = (const float*)d_in[2];
    const float* bp   = (const float*)d_in[3];
    const float* W_ih = (const float*)d_in[4];
    const float* b_ih = (const float*)d_in[6];
    const float* b_hh = (const float*)d_in[7];
    const float* Wh   = (const float*)d_in[10];
    const float* bh   = (const float*)d_in[11];
    float* out = (float*)d_out;

    const int C = in_sizes[11];                 // 1000
    const int B = out_size / C;                 // 512
    const int D = in_sizes[2] / 8;              // 64
    const int T = in_sizes[0] / (B * D);        // 512

    ua_kernel<<<B / 8, 256>>>(x, Wp, bp, W_ih, b_ih, b_hh, T, D);
    ep_kernel<<<B / BPC, 256>>>(Wh, bh, out, C);
}